// round 16
// baseline (speedup 1.0000x reference)
#include <cuda_runtime.h>
#include <cuda_bf16.h>
#include <cstdint>
#include <math.h>

// Problem constants
#define NB 4
#define SEQ 1024
#define CH 1024
#define NH 16
#define DH 64
#define NROWS (NB * SEQ)
#define FFNDIM (4 * CH)
#define ASCALE 0.03125f
#define LNEPS 1e-5f

typedef __nv_bfloat16 bf16;
typedef __nv_bfloat162 bf162;

// ---------------- scratch ----------------------------------------------------
__device__ float x1_buf[(size_t)NROWS * CH];

__device__ bf16 wq_h[CH * CH], wq_l[CH * CH];
__device__ bf16 wk_h[CH * CH], wk_l[CH * CH];
__device__ bf16 wv_h[CH * CH], wv_l[CH * CH];
__device__ bf16 wo_h[CH * CH], wo_l[CH * CH];
__device__ bf16 w1_h[(size_t)FFNDIM * CH], w1_l[(size_t)FFNDIM * CH];
__device__ bf16 w2_h[(size_t)CH * FFNDIM], w2_l[(size_t)CH * FFNDIM];
__device__ bf16 ctx_h[(size_t)NROWS * CH], ctx_l[(size_t)NROWS * CH];
__device__ bf16 mod_h[(size_t)NROWS * CH], mod_l[(size_t)NROWS * CH];
__device__ bf16 ao_h[(size_t)NROWS * CH], ao_l[(size_t)NROWS * CH];
__device__ bf16 hb_h[(size_t)NROWS * FFNDIM], hb_l[(size_t)NROWS * FFNDIM];
__device__ bf16 q_h[(size_t)NROWS * CH];
__device__ bf16 k_h[(size_t)NROWS * CH];
__device__ bf16 v_h[(size_t)NROWS * CH], v_l[(size_t)NROWS * CH];

// ---------------- PTX helpers ------------------------------------------------
__device__ __forceinline__ uint32_t smem_u32(const void* p) {
    uint32_t a;
    asm("{ .reg .u64 t; cvta.to.shared.u64 t, %1; cvt.u32.u64 %0, t; }"
        : "=r"(a) : "l"(p));
    return a;
}
__device__ __forceinline__ void cp_async16(uint32_t sa, const void* ga) {
    asm volatile("cp.async.cg.shared.global [%0], [%1], 16;"
                 :: "r"(sa), "l"(ga) : "memory");
}
#define CP_COMMIT() asm volatile("cp.async.commit_group;" ::: "memory")
#define CP_WAIT(n)  asm volatile("cp.async.wait_group %0;" :: "n"(n) : "memory")

#define LDSM4(r0, r1, r2, r3, addr) \
    asm volatile("ldmatrix.sync.aligned.m8n8.x4.shared.b16 {%0,%1,%2,%3}, [%4];" \
                 : "=r"(r0), "=r"(r1), "=r"(r2), "=r"(r3) : "r"(addr))

#define LDSM4T(r0, r1, r2, r3, addr) \
    asm volatile("ldmatrix.sync.aligned.m8n8.x4.trans.shared.b16 {%0,%1,%2,%3}, [%4];" \
                 : "=r"(r0), "=r"(r1), "=r"(r2), "=r"(r3) : "r"(addr))

#define MMA_BF16(c, a, b) \
    asm volatile( \
        "mma.sync.aligned.m16n8k16.row.col.f32.bf16.bf16.f32 " \
        "{%0,%1,%2,%3}, {%4,%5,%6,%7}, {%8,%9}, {%0,%1,%2,%3};" \
        : "+f"((c)[0]), "+f"((c)[1]), "+f"((c)[2]), "+f"((c)[3]) \
        : "r"((a)[0]), "r"((a)[1]), "r"((a)[2]), "r"((a)[3]), \
          "r"((b)[0]), "r"((b)[1]))

#define MMA_BF16_2(c, a, b0, b1) \
    asm volatile( \
        "mma.sync.aligned.m16n8k16.row.col.f32.bf16.bf16.f32 " \
        "{%0,%1,%2,%3}, {%4,%5,%6,%7}, {%8,%9}, {%0,%1,%2,%3};" \
        : "+f"((c)[0]), "+f"((c)[1]), "+f"((c)[2]), "+f"((c)[3]) \
        : "r"((a)[0]), "r"((a)[1]), "r"((a)[2]), "r"((a)[3]), \
          "r"(b0), "r"(b1))

// GEMM tiles: [128 rows][32 bf16 = 64B], 4 groups of 16B
__device__ __forceinline__ uint32_t sw_off(int row, int g) {
    return (uint32_t)(row * 64 + (((g ^ (row >> 1)) & 3) << 4));
}
// Attention tiles: [rows][64 bf16 = 128B], 8 groups of 16B
__device__ __forceinline__ uint32_t sw128(int row, int g) {
    return (uint32_t)(row * 128 + (((g ^ row) & 7) << 4));
}

__device__ __forceinline__ void split_f(float x, bf16& h, bf16& l) {
    h = __float2bfloat16_rn(x);
    l = __float2bfloat16_rn(x - __bfloat162float(h));
}
__device__ __forceinline__ uint32_t pack_bf2(float a, float b) {
    bf162 t = __floats2bfloat162_rn(a, b);
    return *(uint32_t*)&t;
}

// ---------------- fp32 -> (bf16 hi, bf16 lo) split helper -------------------
__device__ __forceinline__ void split_store(const float* __restrict__ src,
                                            bf16* __restrict__ hi,
                                            bf16* __restrict__ lo, int i) {
    float4 v = ((const float4*)src)[i];
    bf16 h0, h1, h2, h3, l0, l1, l2, l3;
    split_f(v.x, h0, l0); split_f(v.y, h1, l1);
    split_f(v.z, h2, l2); split_f(v.w, h3, l3);
    bf162* hp = (bf162*)(hi + (size_t)i * 4);
    bf162* lp = (bf162*)(lo + (size_t)i * 4);
    hp[0] = bf162(h0, h1); hp[1] = bf162(h2, h3);
    lp[0] = bf162(l0, l1); lp[1] = bf162(l2, l3);
}

// ---------------- LayerNorm + AdaLN modulate body ---------------------------
__device__ __forceinline__ void ln_mod_body(
        const float* __restrict__ X, const float* __restrict__ ada,
        const float* __restrict__ cond,
        bf16* __restrict__ Oh, bf16* __restrict__ Ol,
        int row, int si, int hi) {
    int b = row >> 10;
    int t = threadIdx.x;
    const float4* xr = (const float4*)(X + (size_t)row * CH);
    float4 v = xr[t];

    __shared__ float red[8];
    float s = v.x + v.y + v.z + v.w;
    #pragma unroll
    for (int o = 16; o; o >>= 1) s += __shfl_xor_sync(0xffffffffu, s, o);
    if ((t & 31) == 0) red[t >> 5] = s;
    __syncthreads();
    float tot = 0.f;
    #pragma unroll
    for (int w = 0; w < 8; w++) tot += red[w];
    float mean = tot * (1.0f / CH);

    float dx = v.x - mean, dy = v.y - mean, dz = v.z - mean, dw = v.w - mean;
    float s2 = dx * dx + dy * dy + dz * dz + dw * dw;
    #pragma unroll
    for (int o = 16; o; o >>= 1) s2 += __shfl_xor_sync(0xffffffffu, s2, o);
    __syncthreads();
    if ((t & 31) == 0) red[t >> 5] = s2;
    __syncthreads();
    float tot2 = 0.f;
    #pragma unroll
    for (int w = 0; w < 8; w++) tot2 += red[w];
    float rstd = rsqrtf(tot2 * (1.0f / CH) + LNEPS);

    size_t cb = (size_t)b * 6 * CH;
    float4 sa = *(const float4*)(ada + si * CH + t * 4);
    float4 sc2 = *(const float4*)(cond + cb + si * CH + t * 4);
    float4 ha = *(const float4*)(ada + hi * CH + t * 4);
    float4 hc = *(const float4*)(cond + cb + hi * CH + t * 4);
    float4 sc = make_float4(sa.x + sc2.x, sa.y + sc2.y, sa.z + sc2.z, sa.w + sc2.w);
    float4 sh = make_float4(ha.x + hc.x, ha.y + hc.y, ha.z + hc.z, ha.w + hc.w);
    float m0 = dx * rstd * (1.0f + sc.x) + sh.x;
    float m1 = dy * rstd * (1.0f + sc.y) + sh.y;
    float m2 = dz * rstd * (1.0f + sc.z) + sh.z;
    float m3 = dw * rstd * (1.0f + sc.w) + sh.w;

    bf16 h0, h1, h2, h3, l0, l1, l2, l3;
    split_f(m0, h0, l0); split_f(m1, h1, l1);
    split_f(m2, h2, l2); split_f(m3, h3, l3);
    size_t base = (size_t)row * CH + t * 4;
    bf162* hp = (bf162*)(Oh + base);
    bf162* lp = (bf162*)(Ol + base);
    hp[0] = bf162(h0, h1); hp[1] = bf162(h2, h3);
    lp[0] = bf162(l0, l1); lp[1] = bf162(l2, l3);
}

__global__ void ln_mod_kernel(const float* __restrict__ X,
                              const float* __restrict__ ada,
                              const float* __restrict__ cond,
                              bf16* __restrict__ Oh, bf16* __restrict__ Ol,
                              int si, int hi) {
    ln_mod_body(X, ada, cond, Oh, Ol, blockIdx.x, si, hi);
}

// ---------------- prep kernel: critical splits + LN(x) ----------------------
// z 0..3: split tensor z (ctx, Wq, Wk, Wv); z 4..7: LN rows (z-4)*1024 + x
struct PrepArgs {
    const float* src[4];
    bf16* hi[4];
    bf16* lo[4];
    int n4[4];
    const float* x;
    const float* ada;
    const float* cond;
    bf16 *mh, *ml;
};
__global__ void prep_kernel(PrepArgs a) {
    int z = blockIdx.y;
    if (z < 4) {
        int n4 = a.n4[z];
        int i = blockIdx.x * 1024 + threadIdx.x;
        if (i >= n4) return;
        const float* src = a.src[z];
        bf16* hi = a.hi[z];
        bf16* lo = a.lo[z];
        #pragma unroll
        for (int c = 0; c < 4; c++, i += 256)
            if (i < n4) split_store(src, hi, lo, i);
    } else {
        int row = (z - 4) * 1024 + blockIdx.x;
        ln_mod_body(a.x, a.ada, a.cond, a.mh, a.ml, row, 2, 4);
    }
}

__device__ __forceinline__ float gelu_tanh(float u) {
    float z = 0.7978845608028654f * (u + 0.044715f * u * u * u);
    float e = __expf(-2.0f * z);
    return u / (1.0f + e);
}

// ---------------- bf16-split mma.sync GEMM core ------------------------------
// TERMS==3: dot = Ah*Bh + Ah*Bl + Al*Bh ; TERMS==2: Al dropped/never loaded
#define BKB 32
#define GSTAGES 3
#define PLANE_BYTES 8192
#define STAGE_BYTES (4 * PLANE_BYTES)
#define GEMM_SMEM (GSTAGES * STAGE_BYTES)

// MODE 0: Yf = dot
// MODE 1/3: Yf = xres + (dot + bias[n]) * (gamA[n] + gamC[b*6C + n])
// MODE 2: (Yh, Yl) = split(gelu(dot + bias[n]))
// MODE 4: (Yh, Yl) = split(dot)
// MODE 5: Yh = bf16(dot)
template <int MODE, int TERMS>
__device__ __forceinline__ void gemm_core(
        const bf16* __restrict__ Ah, const bf16* __restrict__ Al,
        const bf16* __restrict__ Bh, const bf16* __restrict__ Bl,
        float* __restrict__ Yf, bf16* __restrict__ Yh, bf16* __restrict__ Yl,
        int N, int K,
        const float* __restrict__ bias, const float* __restrict__ gamA,
        const float* __restrict__ gamC, const float* __restrict__ xres,
        uint32_t smb, int bm, int bn) {
    int tid = threadIdx.x;
    int lane = tid & 31, wid = tid >> 5;
    int wm = wid >> 2;
    int wn = wid & 3;
    const int NC = K / BKB;

    auto issue = [&](int c, int st) {
        uint32_t s0 = smb + st * STAGE_BYTES;
        #pragma unroll
        for (int half = 0; half < 2; half++) {
            int i = half * 256 + tid;
            int row = i >> 2, g = i & 3;
            uint32_t so = sw_off(row, g);
            size_t aoff = (size_t)(bm + row) * K + c * BKB + g * 8;
            size_t boff = (size_t)(bn + row) * K + c * BKB + g * 8;
            cp_async16(s0 + so, Ah + aoff);
            if (TERMS == 3) cp_async16(s0 + PLANE_BYTES + so, Al + aoff);
            cp_async16(s0 + 2 * PLANE_BYTES + so, Bh + boff);
            cp_async16(s0 + 3 * PLANE_BYTES + so, Bl + boff);
        }
        CP_COMMIT();
    };

    issue(0, 0);
    issue(1, 1);

    float c[16][4];
    #pragma unroll
    for (int i = 0; i < 16; i++)
        #pragma unroll
        for (int j = 0; j < 4; j++) c[i][j] = 0.f;

    int a_row_base = wm * 64 + ((lane >> 3) & 1) * 8 + (lane & 7);
    int a_g_base = (lane >> 4);
    int b_row_base = wn * 32 + ((lane >> 4) & 1) * 8 + (lane & 7);
    int b_g_base = ((lane >> 3) & 1);

    int sidx = 0, pidx = 2;
    for (int kt = 0; kt < NC; kt++) {
        if (kt + 1 < NC) { CP_WAIT(1); } else { CP_WAIT(0); }
        __syncthreads();
        if (kt + 2 < NC) issue(kt + 2, pidx);

        uint32_t sAh = smb + sidx * STAGE_BYTES;
        uint32_t sAl = sAh + PLANE_BYTES;
        uint32_t sBh = sAh + 2 * PLANE_BYTES;
        uint32_t sBl = sAh + 3 * PLANE_BYTES;

        #pragma unroll
        for (int ks = 0; ks < 2; ks++) {
            int ag = ks * 2 + a_g_base;
            int bg = ks * 2 + b_g_base;
            uint32_t bh[4][2], bl[4][2];
            #pragma unroll
            for (int tp = 0; tp < 2; tp++) {
                uint32_t so = sw_off(b_row_base + tp * 16, bg);
                uint32_t r0, r1, r2, r3;
                LDSM4(r0, r1, r2, r3, sBh + so);
                bh[tp * 2][0] = r0;     bh[tp * 2][1] = r1;
                bh[tp * 2 + 1][0] = r2; bh[tp * 2 + 1][1] = r3;
                LDSM4(r0, r1, r2, r3, sBl + so);
                bl[tp * 2][0] = r0;     bl[tp * 2][1] = r1;
                bl[tp * 2 + 1][0] = r2; bl[tp * 2 + 1][1] = r3;
            }
            #pragma unroll
            for (int tm = 0; tm < 4; tm++) {
                uint32_t ah[4], al[4];
                uint32_t so = sw_off(a_row_base + tm * 16, ag);
                LDSM4(ah[0], ah[1], ah[2], ah[3], sAh + so);
                if (TERMS == 3) LDSM4(al[0], al[1], al[2], al[3], sAl + so);
                #pragma unroll
                for (int tn = 0; tn < 4; tn++) {
                    MMA_BF16(c[tm * 4 + tn], ah, bh[tn]);
                    MMA_BF16(c[tm * 4 + tn], ah, bl[tn]);
                    if (TERMS == 3) MMA_BF16(c[tm * 4 + tn], al, bh[tn]);
                }
            }
        }
        sidx = (sidx + 1 == GSTAGES) ? 0 : sidx + 1;
        pidx = (pidx + 1 == GSTAGES) ? 0 : pidx + 1;
    }

    #pragma unroll
    for (int tm = 0; tm < 4; tm++) {
        #pragma unroll
        for (int half = 0; half < 2; half++) {
            int row = bm + wm * 64 + tm * 16 + (lane >> 2) + half * 8;
            size_t rbase = (size_t)row * N;
            int bb = row >> 10;
            #pragma unroll
            for (int tn = 0; tn < 4; tn++) {
                int col = bn + wn * 32 + tn * 8 + (lane & 3) * 2;
                float d0 = c[tm * 4 + tn][half * 2 + 0];
                float d1 = c[tm * 4 + tn][half * 2 + 1];
                if (MODE == 0) {
                    *(float2*)(Yf + rbase + col) = make_float2(d0, d1);
                } else if (MODE == 5) {
                    *(bf162*)(Yh + rbase + col) =
                        __floats2bfloat162_rn(d0, d1);
                } else if (MODE == 4) {
                    bf16 h0, h1, l0, l1;
                    split_f(d0, h0, l0);
                    split_f(d1, h1, l1);
                    *(bf162*)(Yh + rbase + col) = bf162(h0, h1);
                    *(bf162*)(Yl + rbase + col) = bf162(l0, l1);
                } else if (MODE == 2) {
                    float2 bi = *(const float2*)(bias + col);
                    d0 = gelu_tanh(d0 + bi.x);
                    d1 = gelu_tanh(d1 + bi.y);
                    bf16 h0, h1, l0, l1;
                    split_f(d0, h0, l0);
                    split_f(d1, h1, l1);
                    *(bf162*)(Yh + rbase + col) = bf162(h0, h1);
                    *(bf162*)(Yl + rbase + col) = bf162(l0, l1);
                } else {
                    float2 bi = *(const float2*)(bias + col);
                    d0 += bi.x; d1 += bi.y;
                    float2 ga = *(const float2*)(gamA + col);
                    float2 gc = *(const float2*)(gamC + (size_t)bb * 6 * CH + col);
                    float2 xr = *(const float2*)(xres + rbase + col);
                    *(float2*)(Yf + rbase + col) =
                        make_float2(xr.x + d0 * (ga.x + gc.x),
                                    xr.y + d1 * (ga.y + gc.y));
                }
            }
        }
    }
}

template <int MODE>
__global__ void __launch_bounds__(256, 2)
gemm_bf3(const bf16* __restrict__ Ah, const bf16* __restrict__ Al,
         const bf16* __restrict__ Bh, const bf16* __restrict__ Bl,
         float* __restrict__ Yf, bf16* __restrict__ Yh, bf16* __restrict__ Yl,
         int M, int N, int K,
         const float* __restrict__ bias, const float* __restrict__ gamA,
         const float* __restrict__ gamC, const float* __restrict__ xres) {
    extern __shared__ char smraw[];
    gemm_core<MODE, 3>(Ah, Al, Bh, Bl, Yf, Yh, Yl, N, K, bias, gamA, gamC,
                       xres, smem_u32(smraw), blockIdx.y * 128,
                       blockIdx.x * 128);
}

// merged Q/K/V projection + deferred weight splits.
// z=0 (Q), z=1 (K): 2-term GEMM, bf16-only output
// z=2 (V): 3-term GEMM, split hi/lo output
// z=3: 256 CTAs perform the Wo/W1/W2 fp32->bf16 splits (needed much later)
struct QkvArgs {
    const bf16 *ah[3], *al[3], *bh[3], *bl[3];
    bf16 *yh[3], *yl[3];
    const float* wsrc[3];
    bf16 *whi[3], *wlo[3];
    int wn4[3];
};
__global__ void __launch_bounds__(256, 2)
gemm_qkv(QkvArgs a) {
    extern __shared__ char smraw[];
    int z = blockIdx.z;
    if (z == 3) {
        int cid = blockIdx.y * 8 + blockIdx.x;      // 0..255
        int base = cid * 256 + threadIdx.x;         // 0..65535
        #pragma unroll
        for (int t = 0; t < 3; t++) {
            int n4 = a.wn4[t];
            const float* src = a.wsrc[t];
            bf16* hi = a.whi[t];
            bf16* lo = a.wlo[t];
            for (int i = base; i < n4; i += 65536)
                split_store(src, hi, lo, i);
        }
        return;
    }
    if (z == 2) {
        gemm_core<4, 3>(a.ah[2], a.al[2], a.bh[2], a.bl[2],
                        nullptr, a.yh[2], a.yl[2], CH, CH,
                        nullptr, nullptr, nullptr, nullptr,
                        smem_u32(smraw), blockIdx.y * 128, blockIdx.x * 128);
    } else {
        gemm_core<5, 2>(a.ah[z], nullptr, a.bh[z], a.bl[z],
                        nullptr, a.yh[z], nullptr, CH, CH,
                        nullptr, nullptr, nullptr, nullptr,
                        smem_u32(smraw), blockIdx.y * 128, blockIdx.x * 128);
    }
}

// ---------------- attention: bf16 QK (Qh*Kh), PV = Ph*Vh + Ph*Vl -------------
#define ATT_STAGE 24576
#define ATT_SMEM (8192 + 2 * ATT_STAGE)

__global__ void __launch_bounds__(128)
attn_mma(const bf16* __restrict__ Qh,
         const bf16* __restrict__ Kh,
         const bf16* __restrict__ Vh, const bf16* __restrict__ Vl,
         const float* __restrict__ bias,
         bf16* __restrict__ Oh, bf16* __restrict__ Ol) {
    extern __shared__ char smraw[];
    uint32_t smb = smem_u32(smraw);
    int tid = threadIdx.x;
    int lane = tid & 31, w = tid >> 5;
    int bh = blockIdx.x;
    int b = bh >> 4, h = bh & 15;
    int q0 = blockIdx.y * 64;

    {
        #pragma unroll
        for (int it = 0; it < 4; it++) {
            int row = it * 16 + (tid >> 3);
            int g = tid & 7;
            cp_async16(smb + sw128(row, g),
                       Qh + (size_t)(b * SEQ + q0 + row) * CH + h * DH + g * 8);
        }
    }
    auto issue_tile = [&](int kt) {
        uint32_t st = smb + 8192 + (kt & 1) * ATT_STAGE;
        const bf16* pp[3] = {Kh, Vh, Vl};
        #pragma unroll
        for (int it = 0; it < 12; it++) {
            int pl = it >> 2;
            int row = (it & 3) * 16 + (tid >> 3);
            int g = tid & 7;
            cp_async16(st + pl * 8192 + sw128(row, g),
                       pp[pl] + (size_t)(b * SEQ + kt * 64 + row) * CH + h * DH + g * 8);
        }
    };
    issue_tile(0);
    CP_COMMIT();

    const float* bp0 = bias +
        ((size_t)(b * NH + h) * SEQ + q0 + w * 16 + (lane >> 2)) * SEQ + (lane & 3) * 2;

    float2 bufA[8], bufB[8];
    #pragma unroll
    for (int n = 0; n < 8; n++) {
        bufA[n] = *(const float2*)(bp0 + n * 8);
        bufB[n] = *(const float2*)(bp0 + (size_t)8 * SEQ + n * 8);
    }

    CP_WAIT(0);
    __syncthreads();

    uint32_t qhf[4][4];
    {
        int qrow = w * 16 + (lane & 15);
        #pragma unroll
        for (int ks = 0; ks < 4; ks++) {
            uint32_t so = sw128(qrow, ks * 2 + (lane >> 4));
            LDSM4(qhf[ks][0], qhf[ks][1], qhf[ks][2], qhf[ks][3], smb + so);
        }
    }

    float o[8][4];
    #pragma unroll
    for (int n = 0; n < 8; n++)
        #pragma unroll
        for (int j = 0; j < 4; j++) o[n][j] = 0.f;
    float miA = -1e30f, miB = -1e30f, liA = 0.f, liB = 0.f;

    for (int kt = 0; kt < 16; kt++) {
        if (kt + 1 < 16) { issue_tile(kt + 1); CP_COMMIT(); }

        uint32_t sKh = smb + 8192 + (kt & 1) * ATT_STAGE;
        uint32_t sVh = sKh + 8192;
        uint32_t sVl = sKh + 16384;

        float s[8][4];
        #pragma unroll
        for (int n = 0; n < 8; n++)
            #pragma unroll
            for (int j = 0; j < 4; j++) s[n][j] = 0.f;

        int krow_base = ((lane >> 4) & 1) * 8 + (lane & 7);
        int kg_base = (lane >> 3) & 1;
        #pragma unroll
        for (int ks = 0; ks < 4; ks++) {
            int kg = ks * 2 + kg_base;
            #pragma unroll
            for (int np = 0; np < 4; np++) {
                uint32_t so = sw128(np * 16 + krow_base, kg);
                uint32_t h0, h1, h2, h3;
                LDSM4(h0, h1, h2, h3, sKh + so);
                MMA_BF16_2(s[np * 2], qhf[ks], h0, h1);
                MMA_BF16_2(s[np * 2 + 1], qhf[ks], h2, h3);
            }
        }

        #pragma unroll
        for (int n = 0; n < 8; n++) {
            s[n][0] = fmaf(s[n][0], ASCALE, bufA[n].x);
            s[n][1] = fmaf(s[n][1], ASCALE, bufA[n].y);
            s[n][2] = fmaf(s[n][2], ASCALE, bufB[n].x);
            s[n][3] = fmaf(s[n][3], ASCALE, bufB[n].y);
        }
        if (kt + 1 < 16) {
            const float* bp = bp0 + (kt + 1) * 64;
            #pragma unroll
            for (int n = 0; n < 8; n++) {
                bufA[n] = *(const float2*)(bp + n * 8);
                bufB[n] = *(const float2*)(bp + (size_t)8 * SEQ + n * 8);
            }
        }

        float mA = -1e30f, mB = -1e30f;
        #pragma unroll
        for (int n = 0; n < 8; n++) {
            mA = fmaxf(mA, fmaxf(s[n][0], s[n][1]));
            mB = fmaxf(mB, fmaxf(s[n][2], s[n][3]));
        }
        mA = fmaxf(mA, __shfl_xor_sync(0xffffffffu, mA, 1));
        mA = fmaxf(mA, __shfl_xor_sync(0xffffffffu, mA, 2));
        mB = fmaxf(mB, __shfl_xor_sync(0xffffffffu, mB, 1));
        mB = fmaxf(mB, __shfl_xor_sync(0xffffffffu, mB, 2));
        float mnA = fmaxf(miA, mA), mnB = fmaxf(miB, mB);
        float corrA = __expf(miA - mnA), corrB = __expf(miB - mnB);
        miA = mnA; miB = mnB;
        float rsA = 0.f, rsB = 0.f;
        #pragma unroll
        for (int n = 0; n < 8; n++) {
            s[n][0] = __expf(s[n][0] - mnA);
            s[n][1] = __expf(s[n][1] - mnA);
            s[n][2] = __expf(s[n][2] - mnB);
            s[n][3] = __expf(s[n][3] - mnB);
            rsA += s[n][0] + s[n][1];
            rsB += s[n][2] + s[n][3];
        }
        rsA += __shfl_xor_sync(0xffffffffu, rsA, 1);
        rsA += __shfl_xor_sync(0xffffffffu, rsA, 2);
        rsB += __shfl_xor_sync(0xffffffffu, rsB, 1);
        rsB += __shfl_xor_sync(0xffffffffu, rsB, 2);
        liA = liA * corrA + rsA;
        liB = liB * corrB + rsB;
        #pragma unroll
        for (int n = 0; n < 8; n++) {
            o[n][0] *= corrA; o[n][1] *= corrA;
            o[n][2] *= corrB; o[n][3] *= corrB;
        }

        int vrow_base = ((lane >> 3) & 1) * 8 + (lane & 7);
        int vg_base = (lane >> 4) & 1;
        #pragma unroll
        for (int kk = 0; kk < 4; kk++) {
            uint32_t pah[4];
            #pragma unroll
            for (int q = 0; q < 2; q++) {
                int nf = kk * 2 + q;
                pah[q * 2 + 0] = pack_bf2(s[nf][0], s[nf][1]);
                pah[q * 2 + 1] = pack_bf2(s[nf][2], s[nf][3]);
            }
            #pragma unroll
            for (int dp = 0; dp < 4; dp++) {
                uint32_t so = sw128(kk * 16 + vrow_base, dp * 2 + vg_base);
                uint32_t r0, r1, r2, r3;
                LDSM4T(r0, r1, r2, r3, sVh + so);
                MMA_BF16_2(o[dp * 2], pah, r0, r1);
                MMA_BF16_2(o[dp * 2 + 1], pah, r2, r3);
                LDSM4T(r0, r1, r2, r3, sVl + so);
                MMA_BF16_2(o[dp * 2], pah, r0, r1);
                MMA_BF16_2(o[dp * 2 + 1], pah, r2, r3);
            }
        }

        if (kt + 1 < 16) { CP_WAIT(0); __syncthreads(); }
    }

    float invA = 1.0f / liA, invB = 1.0f / liB;
    size_t rowA = (size_t)(b * SEQ + q0 + w * 16 + (lane >> 2));
    #pragma unroll
    for (int n = 0; n < 8; n++) {
        int col = h * DH + n * 8 + (lane & 3) * 2;
        float f0 = o[n][0] * invA, f1 = o[n][1] * invA;
        float f2 = o[n][2] * invB, f3 = o[n][3] * invB;
        bf16 h0, h1, h2, h3, l0, l1, l2, l3;
        split_f(f0, h0, l0); split_f(f1, h1, l1);
        split_f(f2, h2, l2); split_f(f3, h3, l3);
        *(bf162*)(Oh + rowA * CH + col) = bf162(h0, h1);
        *(bf162*)(Ol + rowA * CH + col) = bf162(l0, l1);
        *(bf162*)(Oh + (rowA + 8) * CH + col) = bf162(h2, h3);
        *(bf162*)(Ol + (rowA + 8) * CH + col) = bf162(l2, l3);
    }
}

// ---------------- launch ------------------------------------------------------
extern "C" void kernel_launch(void* const* d_in, const int* in_sizes, int n_in,
                              void* d_out, int out_size) {
    const float* x         = (const float*)d_in[0];
    const float* context   = (const float*)d_in[1];
    const float* cond_BD   = (const float*)d_in[2];
    const float* attn_bias = (const float*)d_in[3];
    const float* ada_gss   = (const float*)d_in[4];
    const float* Wq        = (const float*)d_in[5];
    const float* Wk        = (const float*)d_in[6];
    const float* Wv        = (const float*)d_in[7];
    const float* Wo        = (const float*)d_in[8];
    const float* bo        = (const float*)d_in[9];
    const float* W1        = (const float*)d_in[10];
    const float* b1        = (const float*)d_in[11];
    const float* W2        = (const float*)d_in[12];
    const float* b2        = (const float*)d_in[13];
    float* out = (float*)d_out;

    float* x1_p;
    cudaGetSymbolAddress((void**)&x1_p, x1_buf);

    bf16 *wqh, *wql, *wkh, *wkl, *wvh, *wvl, *woh, *wol;
    bf16 *w1h, *w1l, *w2h, *w2l, *ch_, *cl_, *mh, *ml, *aoh, *aol, *hh, *hl;
    bf16 *qh, *kh, *vh, *vl;
    cudaGetSymbolAddress((void**)&wqh, wq_h); cudaGetSymbolAddress((void**)&wql, wq_l);
    cudaGetSymbolAddress((void**)&wkh, wk_h); cudaGetSymbolAddress((void**)&wkl, wk_l);
    cudaGetSymbolAddress((void**)&wvh, wv_h); cudaGetSymbolAddress((void**)&wvl, wv_l);
    cudaGetSymbolAddress((void**)&woh, wo_h); cudaGetSymbolAddress((void**)&wol, wo_l);
    cudaGetSymbolAddress((void**)&w1h, w1_h); cudaGetSymbolAddress((void**)&w1l, w1_l);
    cudaGetSymbolAddress((void**)&w2h, w2_h); cudaGetSymbolAddress((void**)&w2l, w2_l);
    cudaGetSymbolAddress((void**)&ch_, ctx_h); cudaGetSymbolAddress((void**)&cl_, ctx_l);
    cudaGetSymbolAddress((void**)&mh, mod_h);  cudaGetSymbolAddress((void**)&ml, mod_l);
    cudaGetSymbolAddress((void**)&aoh, ao_h);  cudaGetSymbolAddress((void**)&aol, ao_l);
    cudaGetSymbolAddress((void**)&hh, hb_h);   cudaGetSymbolAddress((void**)&hl, hb_l);
    cudaGetSymbolAddress((void**)&qh, q_h);
    cudaGetSymbolAddress((void**)&kh, k_h);
    cudaGetSymbolAddress((void**)&vh, v_h);    cudaGetSymbolAddress((void**)&vl, v_l);

    cudaFuncSetAttribute(attn_mma,
                         cudaFuncAttributeMaxDynamicSharedMemorySize, ATT_SMEM);
    cudaFuncSetAttribute(gemm_qkv,
                         cudaFuncAttributeMaxDynamicSharedMemorySize, GEMM_SMEM);
    cudaFuncSetAttribute(gemm_bf3<1>,
                         cudaFuncAttributeMaxDynamicSharedMemorySize, GEMM_SMEM);
    cudaFuncSetAttribute(gemm_bf3<2>,
                         cudaFuncAttributeMaxDynamicSharedMemorySize, GEMM_SMEM);
    cudaFuncSetAttribute(gemm_bf3<3>,
                         cudaFuncAttributeMaxDynamicSharedMemorySize, GEMM_SMEM);

    // 0: critical splits (ctx, Wq, Wk, Wv) + LN(x)
    PrepArgs pa;
    pa.src[0] = context; pa.hi[0] = ch_; pa.lo[0] = cl_; pa.n4[0] = NROWS * CH / 4;
    pa.src[1] = Wq;      pa.hi[1] = wqh; pa.lo[1] = wql; pa.n4[1] = CH * CH / 4;
    pa.src[2] = Wk;      pa.hi[2] = wkh; pa.lo[2] = wkl; pa.n4[2] = CH * CH / 4;
    pa.src[3] = Wv;      pa.hi[3] = wvh; pa.lo[3] = wvl; pa.n4[3] = CH * CH / 4;
    pa.x = x; pa.ada = ada_gss; pa.cond = cond_BD; pa.mh = mh; pa.ml = ml;
    prep_kernel<<<dim3(1024, 8), 256>>>(pa);

    // 1: Q/K/V projections + deferred Wo/W1/W2 splits (z=3)
    QkvArgs qa;
    qa.ah[0] = mh;  qa.al[0] = nullptr; qa.bh[0] = wqh; qa.bl[0] = wql;
    qa.yh[0] = qh;  qa.yl[0] = nullptr;
    qa.ah[1] = ch_; qa.al[1] = nullptr; qa.bh[1] = wkh; qa.bl[1] = wkl;
    qa.yh[1] = kh;  qa.yl[1] = nullptr;
    qa.ah[2] = ch_; qa.al[2] = cl_;     qa.bh[2] = wvh; qa.bl[2] = wvl;
    qa.yh[2] = vh;  qa.yl[2] = vl;
    qa.wsrc[0] = Wo; qa.whi[0] = woh; qa.wlo[0] = wol; qa.wn4[0] = CH * CH / 4;
    qa.wsrc[1] = W1; qa.whi[1] = w1h; qa.wlo[1] = w1l; qa.wn4[1] = FFNDIM * CH / 4;
    qa.wsrc[2] = W2; qa.whi[2] = w2h; qa.wlo[2] = w2l; qa.wn4[2] = FFNDIM * CH / 4;
    gemm_qkv<<<dim3(8, 32, 4), 256, GEMM_SMEM>>>(qa);

    // 2: fused attention
    attn_mma<<<dim3(NB * NH, SEQ / 64), 128, ATT_SMEM>>>(qh, kh, vh, vl,
                                                         attn_bias, aoh, aol);

    // 3: x1 = x + (ao @ Wo^T + bo) * gamma1
    gemm_bf3<1><<<dim3(8, 32), 256, GEMM_SMEM>>>(aoh, aol, woh, wol, x1_p,
                                                 nullptr, nullptr,
                                                 NROWS, CH, CH,
                                                 bo, ada_gss, cond_BD, x);

    // 4: mod_f = LN(x1)*(1+scale2)+shift2
    ln_mod_kernel<<<NROWS, 256>>>(x1_p, ada_gss, cond_BD, mh, ml, 3, 5);

    // 5: h = gelu(mod_f @ W1^T + b1)
    gemm_bf3<2><<<dim3(32, 32), 256, GEMM_SMEM>>>(mh, ml, w1h, w1l, nullptr,
                                                  hh, hl,
                                                  NROWS, FFNDIM, CH,
                                                  b1, nullptr, nullptr, nullptr);

    // 6: out = x1 + (h @ W2^T + b2) * gamma2
    gemm_bf3<3><<<dim3(8, 32), 256, GEMM_SMEM>>>(hh, hl, w2h, w2l, out,
                                                 nullptr, nullptr,
                                                 NROWS, CH, FFNDIM,
                                                 b2, ada_gss + CH, cond_BD + CH,
                                                 x1_p);
}

// round 17
// speedup vs baseline: 1.5322x; 1.5322x over previous
#include <cuda_runtime.h>
#include <cuda_bf16.h>
#include <cstdint>
#include <math.h>

// Problem constants
#define NB 4
#define SEQ 1024
#define CH 1024
#define NH 16
#define DH 64
#define NROWS (NB * SEQ)
#define FFNDIM (4 * CH)
#define ASCALE 0.03125f
#define LNEPS 1e-5f

typedef __nv_bfloat16 bf16;
typedef __nv_bfloat162 bf162;

// ---------------- scratch ----------------------------------------------------
__device__ float x1_buf[(size_t)NROWS * CH];

__device__ bf16 wq_h[CH * CH], wq_l[CH * CH];
__device__ bf16 wk_h[CH * CH], wk_l[CH * CH];
__device__ bf16 wv_h[CH * CH], wv_l[CH * CH];
__device__ bf16 wo_h[CH * CH], wo_l[CH * CH];
__device__ bf16 w1_h[(size_t)FFNDIM * CH], w1_l[(size_t)FFNDIM * CH];
__device__ bf16 w2_h[(size_t)CH * FFNDIM], w2_l[(size_t)CH * FFNDIM];
__device__ bf16 ctx_h[(size_t)NROWS * CH], ctx_l[(size_t)NROWS * CH];
__device__ bf16 mod_h[(size_t)NROWS * CH], mod_l[(size_t)NROWS * CH];
__device__ bf16 ao_h[(size_t)NROWS * CH], ao_l[(size_t)NROWS * CH];
__device__ bf16 hb_h[(size_t)NROWS * FFNDIM], hb_l[(size_t)NROWS * FFNDIM];
__device__ bf16 q_h[(size_t)NROWS * CH];
__device__ bf16 k_h[(size_t)NROWS * CH];
__device__ bf16 v_h[(size_t)NROWS * CH], v_l[(size_t)NROWS * CH];

// ---------------- PTX helpers ------------------------------------------------
__device__ __forceinline__ uint32_t smem_u32(const void* p) {
    uint32_t a;
    asm("{ .reg .u64 t; cvta.to.shared.u64 t, %1; cvt.u32.u64 %0, t; }"
        : "=r"(a) : "l"(p));
    return a;
}
__device__ __forceinline__ void cp_async16(uint32_t sa, const void* ga) {
    asm volatile("cp.async.cg.shared.global [%0], [%1], 16;"
                 :: "r"(sa), "l"(ga) : "memory");
}
#define CP_COMMIT() asm volatile("cp.async.commit_group;" ::: "memory")
#define CP_WAIT(n)  asm volatile("cp.async.wait_group %0;" :: "n"(n) : "memory")

#define LDSM4(r0, r1, r2, r3, addr) \
    asm volatile("ldmatrix.sync.aligned.m8n8.x4.shared.b16 {%0,%1,%2,%3}, [%4];" \
                 : "=r"(r0), "=r"(r1), "=r"(r2), "=r"(r3) : "r"(addr))

#define LDSM4T(r0, r1, r2, r3, addr) \
    asm volatile("ldmatrix.sync.aligned.m8n8.x4.trans.shared.b16 {%0,%1,%2,%3}, [%4];" \
                 : "=r"(r0), "=r"(r1), "=r"(r2), "=r"(r3) : "r"(addr))

#define MMA_BF16(c, a, b) \
    asm volatile( \
        "mma.sync.aligned.m16n8k16.row.col.f32.bf16.bf16.f32 " \
        "{%0,%1,%2,%3}, {%4,%5,%6,%7}, {%8,%9}, {%0,%1,%2,%3};" \
        : "+f"((c)[0]), "+f"((c)[1]), "+f"((c)[2]), "+f"((c)[3]) \
        : "r"((a)[0]), "r"((a)[1]), "r"((a)[2]), "r"((a)[3]), \
          "r"((b)[0]), "r"((b)[1]))

#define MMA_BF16_2(c, a, b0, b1) \
    asm volatile( \
        "mma.sync.aligned.m16n8k16.row.col.f32.bf16.bf16.f32 " \
        "{%0,%1,%2,%3}, {%4,%5,%6,%7}, {%8,%9}, {%0,%1,%2,%3};" \
        : "+f"((c)[0]), "+f"((c)[1]), "+f"((c)[2]), "+f"((c)[3]) \
        : "r"((a)[0]), "r"((a)[1]), "r"((a)[2]), "r"((a)[3]), \
          "r"(b0), "r"(b1))

// GEMM tiles: [128 rows][32 bf16 = 64B], 4 groups of 16B
__device__ __forceinline__ uint32_t sw_off(int row, int g) {
    return (uint32_t)(row * 64 + (((g ^ (row >> 1)) & 3) << 4));
}
// Attention tiles: [rows][64 bf16 = 128B], 8 groups of 16B
__device__ __forceinline__ uint32_t sw128(int row, int g) {
    return (uint32_t)(row * 128 + (((g ^ row) & 7) << 4));
}

__device__ __forceinline__ void split_f(float x, bf16& h, bf16& l) {
    h = __float2bfloat16_rn(x);
    l = __float2bfloat16_rn(x - __bfloat162float(h));
}
__device__ __forceinline__ uint32_t pack_bf2(float a, float b) {
    bf162 t = __floats2bfloat162_rn(a, b);
    return *(uint32_t*)&t;
}

// ---------------- fp32 -> (bf16 hi, bf16 lo) split helper -------------------
__device__ __forceinline__ void split_store(const float* __restrict__ src,
                                            bf16* __restrict__ hi,
                                            bf16* __restrict__ lo, int i) {
    float4 v = ((const float4*)src)[i];
    bf16 h0, h1, h2, h3, l0, l1, l2, l3;
    split_f(v.x, h0, l0); split_f(v.y, h1, l1);
    split_f(v.z, h2, l2); split_f(v.w, h3, l3);
    bf162* hp = (bf162*)(hi + (size_t)i * 4);
    bf162* lp = (bf162*)(lo + (size_t)i * 4);
    hp[0] = bf162(h0, h1); hp[1] = bf162(h2, h3);
    lp[0] = bf162(l0, l1); lp[1] = bf162(l2, l3);
}

// ---------------- LayerNorm + AdaLN modulate body ---------------------------
__device__ __forceinline__ void ln_mod_body(
        const float* __restrict__ X, const float* __restrict__ ada,
        const float* __restrict__ cond,
        bf16* __restrict__ Oh, bf16* __restrict__ Ol,
        int row, int si, int hi) {
    int b = row >> 10;
    int t = threadIdx.x;
    const float4* xr = (const float4*)(X + (size_t)row * CH);
    float4 v = xr[t];

    __shared__ float red[8];
    float s = v.x + v.y + v.z + v.w;
    #pragma unroll
    for (int o = 16; o; o >>= 1) s += __shfl_xor_sync(0xffffffffu, s, o);
    if ((t & 31) == 0) red[t >> 5] = s;
    __syncthreads();
    float tot = 0.f;
    #pragma unroll
    for (int w = 0; w < 8; w++) tot += red[w];
    float mean = tot * (1.0f / CH);

    float dx = v.x - mean, dy = v.y - mean, dz = v.z - mean, dw = v.w - mean;
    float s2 = dx * dx + dy * dy + dz * dz + dw * dw;
    #pragma unroll
    for (int o = 16; o; o >>= 1) s2 += __shfl_xor_sync(0xffffffffu, s2, o);
    __syncthreads();
    if ((t & 31) == 0) red[t >> 5] = s2;
    __syncthreads();
    float tot2 = 0.f;
    #pragma unroll
    for (int w = 0; w < 8; w++) tot2 += red[w];
    float rstd = rsqrtf(tot2 * (1.0f / CH) + LNEPS);

    size_t cb = (size_t)b * 6 * CH;
    float4 sa = *(const float4*)(ada + si * CH + t * 4);
    float4 sc2 = *(const float4*)(cond + cb + si * CH + t * 4);
    float4 ha = *(const float4*)(ada + hi * CH + t * 4);
    float4 hc = *(const float4*)(cond + cb + hi * CH + t * 4);
    float4 sc = make_float4(sa.x + sc2.x, sa.y + sc2.y, sa.z + sc2.z, sa.w + sc2.w);
    float4 sh = make_float4(ha.x + hc.x, ha.y + hc.y, ha.z + hc.z, ha.w + hc.w);
    float m0 = dx * rstd * (1.0f + sc.x) + sh.x;
    float m1 = dy * rstd * (1.0f + sc.y) + sh.y;
    float m2 = dz * rstd * (1.0f + sc.z) + sh.z;
    float m3 = dw * rstd * (1.0f + sc.w) + sh.w;

    bf16 h0, h1, h2, h3, l0, l1, l2, l3;
    split_f(m0, h0, l0); split_f(m1, h1, l1);
    split_f(m2, h2, l2); split_f(m3, h3, l3);
    size_t base = (size_t)row * CH + t * 4;
    bf162* hp = (bf162*)(Oh + base);
    bf162* lp = (bf162*)(Ol + base);
    hp[0] = bf162(h0, h1); hp[1] = bf162(h2, h3);
    lp[0] = bf162(l0, l1); lp[1] = bf162(l2, l3);
}

__global__ void ln_mod_kernel(const float* __restrict__ X,
                              const float* __restrict__ ada,
                              const float* __restrict__ cond,
                              bf16* __restrict__ Oh, bf16* __restrict__ Ol,
                              int si, int hi) {
    ln_mod_body(X, ada, cond, Oh, Ol, blockIdx.x, si, hi);
}

// ---------------- mega prep kernel: 7 splits + LN(x) in one launch ----------
struct PrepArgs {
    const float* src[7];
    bf16* hi[7];
    bf16* lo[7];
    int n4[7];
    const float* x;
    const float* ada;
    const float* cond;
    bf16 *mh, *ml;
};
__global__ void prep_kernel(PrepArgs a) {
    int z = blockIdx.y;
    if (z < 7) {
        int n4 = a.n4[z];
        int i = blockIdx.x * 1024 + threadIdx.x;
        if (i >= n4) return;
        const float* src = a.src[z];
        bf16* hi = a.hi[z];
        bf16* lo = a.lo[z];
        #pragma unroll
        for (int c = 0; c < 4; c++, i += 256)
            if (i < n4) split_store(src, hi, lo, i);
    } else {
        int row = (z - 7) * 1024 + blockIdx.x;
        ln_mod_body(a.x, a.ada, a.cond, a.mh, a.ml, row, 2, 4);
    }
}

__device__ __forceinline__ float gelu_tanh(float u) {
    float z = 0.7978845608028654f * (u + 0.044715f * u * u * u);
    float e = __expf(-2.0f * z);
    return u / (1.0f + e);
}

// ---------------- bf16-split mma.sync GEMM core ------------------------------
// TERMS==3: dot = Ah*Bh + Ah*Bl + Al*Bh (full split)
// TERMS==2: dot = Ah*Bh + Ah*Bl        (A-lo dropped; Al never loaded)
#define BKB 32
#define GSTAGES 3
#define PLANE_BYTES 8192
#define STAGE_BYTES (4 * PLANE_BYTES)
#define GEMM_SMEM (GSTAGES * STAGE_BYTES)

// MODE 0: Yf = dot
// MODE 1/3: Yf = xres + (dot + bias[n]) * (gamA[n] + gamC[b*6C + n])
// MODE 2: (Yh, Yl) = split(gelu(dot + bias[n]))
// MODE 4: (Yh, Yl) = split(dot)
// MODE 5: Yh = bf16(dot)           (lo plane not written)
template <int MODE, int TERMS>
__device__ __forceinline__ void gemm_core(
        const bf16* __restrict__ Ah, const bf16* __restrict__ Al,
        const bf16* __restrict__ Bh, const bf16* __restrict__ Bl,
        float* __restrict__ Yf, bf16* __restrict__ Yh, bf16* __restrict__ Yl,
        int N, int K,
        const float* __restrict__ bias, const float* __restrict__ gamA,
        const float* __restrict__ gamC, const float* __restrict__ xres,
        uint32_t smb, int bm, int bn) {
    int tid = threadIdx.x;
    int lane = tid & 31, wid = tid >> 5;
    int wm = wid >> 2;
    int wn = wid & 3;
    const int NC = K / BKB;

    auto issue = [&](int c, int st) {
        uint32_t s0 = smb + st * STAGE_BYTES;
        #pragma unroll
        for (int half = 0; half < 2; half++) {
            int i = half * 256 + tid;
            int row = i >> 2, g = i & 3;
            uint32_t so = sw_off(row, g);
            size_t aoff = (size_t)(bm + row) * K + c * BKB + g * 8;
            size_t boff = (size_t)(bn + row) * K + c * BKB + g * 8;
            cp_async16(s0 + so, Ah + aoff);
            if (TERMS == 3) cp_async16(s0 + PLANE_BYTES + so, Al + aoff);
            cp_async16(s0 + 2 * PLANE_BYTES + so, Bh + boff);
            cp_async16(s0 + 3 * PLANE_BYTES + so, Bl + boff);
        }
        CP_COMMIT();
    };

    issue(0, 0);
    issue(1, 1);

    float c[16][4];
    #pragma unroll
    for (int i = 0; i < 16; i++)
        #pragma unroll
        for (int j = 0; j < 4; j++) c[i][j] = 0.f;

    int a_row_base = wm * 64 + ((lane >> 3) & 1) * 8 + (lane & 7);
    int a_g_base = (lane >> 4);
    int b_row_base = wn * 32 + ((lane >> 4) & 1) * 8 + (lane & 7);
    int b_g_base = ((lane >> 3) & 1);

    int sidx = 0, pidx = 2;
    for (int kt = 0; kt < NC; kt++) {
        if (kt + 1 < NC) { CP_WAIT(1); } else { CP_WAIT(0); }
        __syncthreads();
        if (kt + 2 < NC) issue(kt + 2, pidx);

        uint32_t sAh = smb + sidx * STAGE_BYTES;
        uint32_t sAl = sAh + PLANE_BYTES;
        uint32_t sBh = sAh + 2 * PLANE_BYTES;
        uint32_t sBl = sAh + 3 * PLANE_BYTES;

        #pragma unroll
        for (int ks = 0; ks < 2; ks++) {
            int ag = ks * 2 + a_g_base;
            int bg = ks * 2 + b_g_base;
            uint32_t bh[4][2], bl[4][2];
            #pragma unroll
            for (int tp = 0; tp < 2; tp++) {
                uint32_t so = sw_off(b_row_base + tp * 16, bg);
                uint32_t r0, r1, r2, r3;
                LDSM4(r0, r1, r2, r3, sBh + so);
                bh[tp * 2][0] = r0;     bh[tp * 2][1] = r1;
                bh[tp * 2 + 1][0] = r2; bh[tp * 2 + 1][1] = r3;
                LDSM4(r0, r1, r2, r3, sBl + so);
                bl[tp * 2][0] = r0;     bl[tp * 2][1] = r1;
                bl[tp * 2 + 1][0] = r2; bl[tp * 2 + 1][1] = r3;
            }
            #pragma unroll
            for (int tm = 0; tm < 4; tm++) {
                uint32_t ah[4], al[4];
                uint32_t so = sw_off(a_row_base + tm * 16, ag);
                LDSM4(ah[0], ah[1], ah[2], ah[3], sAh + so);
                if (TERMS == 3) LDSM4(al[0], al[1], al[2], al[3], sAl + so);
                #pragma unroll
                for (int tn = 0; tn < 4; tn++) {
                    MMA_BF16(c[tm * 4 + tn], ah, bh[tn]);
                    MMA_BF16(c[tm * 4 + tn], ah, bl[tn]);
                    if (TERMS == 3) MMA_BF16(c[tm * 4 + tn], al, bh[tn]);
                }
            }
        }
        sidx = (sidx + 1 == GSTAGES) ? 0 : sidx + 1;
        pidx = (pidx + 1 == GSTAGES) ? 0 : pidx + 1;
    }

    #pragma unroll
    for (int tm = 0; tm < 4; tm++) {
        #pragma unroll
        for (int half = 0; half < 2; half++) {
            int row = bm + wm * 64 + tm * 16 + (lane >> 2) + half * 8;
            size_t rbase = (size_t)row * N;
            int bb = row >> 10;
            #pragma unroll
            for (int tn = 0; tn < 4; tn++) {
                int col = bn + wn * 32 + tn * 8 + (lane & 3) * 2;
                float d0 = c[tm * 4 + tn][half * 2 + 0];
                float d1 = c[tm * 4 + tn][half * 2 + 1];
                if (MODE == 0) {
                    *(float2*)(Yf + rbase + col) = make_float2(d0, d1);
                } else if (MODE == 5) {
                    *(bf162*)(Yh + rbase + col) =
                        __floats2bfloat162_rn(d0, d1);
                } else if (MODE == 4) {
                    bf16 h0, h1, l0, l1;
                    split_f(d0, h0, l0);
                    split_f(d1, h1, l1);
                    *(bf162*)(Yh + rbase + col) = bf162(h0, h1);
                    *(bf162*)(Yl + rbase + col) = bf162(l0, l1);
                } else if (MODE == 2) {
                    float2 bi = *(const float2*)(bias + col);
                    d0 = gelu_tanh(d0 + bi.x);
                    d1 = gelu_tanh(d1 + bi.y);
                    bf16 h0, h1, l0, l1;
                    split_f(d0, h0, l0);
                    split_f(d1, h1, l1);
                    *(bf162*)(Yh + rbase + col) = bf162(h0, h1);
                    *(bf162*)(Yl + rbase + col) = bf162(l0, l1);
                } else {
                    float2 bi = *(const float2*)(bias + col);
                    d0 += bi.x; d1 += bi.y;
                    float2 ga = *(const float2*)(gamA + col);
                    float2 gc = *(const float2*)(gamC + (size_t)bb * 6 * CH + col);
                    float2 xr = *(const float2*)(xres + rbase + col);
                    *(float2*)(Yf + rbase + col) =
                        make_float2(xr.x + d0 * (ga.x + gc.x),
                                    xr.y + d1 * (ga.y + gc.y));
                }
            }
        }
    }
}

template <int MODE>
__global__ void __launch_bounds__(256, 2)
gemm_bf3(const bf16* __restrict__ Ah, const bf16* __restrict__ Al,
         const bf16* __restrict__ Bh, const bf16* __restrict__ Bl,
         float* __restrict__ Yf, bf16* __restrict__ Yh, bf16* __restrict__ Yl,
         int M, int N, int K,
         const float* __restrict__ bias, const float* __restrict__ gamA,
         const float* __restrict__ gamC, const float* __restrict__ xres) {
    extern __shared__ char smraw[];
    gemm_core<MODE, 3>(Ah, Al, Bh, Bl, Yf, Yh, Yl, N, K, bias, gamA, gamC,
                       xres, smem_u32(smraw), blockIdx.y * 128,
                       blockIdx.x * 128);
}

// merged Q/K/V projection.
// z=0 (Q), z=1 (K): 2-term GEMM, bf16-only output (lo planes never consumed)
// z=2 (V): 3-term GEMM, split hi/lo output
struct QkvArgs {
    const bf16 *ah[3], *al[3], *bh[3], *bl[3];
    bf16 *yh[3], *yl[3];
};
__global__ void __launch_bounds__(256, 2)
gemm_qkv(QkvArgs a) {
    extern __shared__ char smraw[];
    int z = blockIdx.z;
    if (z == 2) {
        gemm_core<4, 3>(a.ah[2], a.al[2], a.bh[2], a.bl[2],
                        nullptr, a.yh[2], a.yl[2], CH, CH,
                        nullptr, nullptr, nullptr, nullptr,
                        smem_u32(smraw), blockIdx.y * 128, blockIdx.x * 128);
    } else {
        gemm_core<5, 2>(a.ah[z], nullptr, a.bh[z], a.bl[z],
                        nullptr, a.yh[z], nullptr, CH, CH,
                        nullptr, nullptr, nullptr, nullptr,
                        smem_u32(smraw), blockIdx.y * 128, blockIdx.x * 128);
    }
}

// ---------------- attention: bf16 QK (Qh*Kh), PV = Ph*Vh + Ph*Vl -------------
// smem: Qh (8KB) + 2 stages x (Kh,Vh,Vl) (48KB) = 56KB
#define ATT_STAGE 24576
#define ATT_SMEM (8192 + 2 * ATT_STAGE)

__global__ void __launch_bounds__(128)
attn_mma(const bf16* __restrict__ Qh,
         const bf16* __restrict__ Kh,
         const bf16* __restrict__ Vh, const bf16* __restrict__ Vl,
         const float* __restrict__ bias,
         bf16* __restrict__ Oh, bf16* __restrict__ Ol) {
    extern __shared__ char smraw[];
    uint32_t smb = smem_u32(smraw);
    int tid = threadIdx.x;
    int lane = tid & 31, w = tid >> 5;
    int bh = blockIdx.x;
    int b = bh >> 4, h = bh & 15;
    int q0 = blockIdx.y * 64;

    {
        #pragma unroll
        for (int it = 0; it < 4; it++) {
            int row = it * 16 + (tid >> 3);
            int g = tid & 7;
            cp_async16(smb + sw128(row, g),
                       Qh + (size_t)(b * SEQ + q0 + row) * CH + h * DH + g * 8);
        }
    }
    auto issue_tile = [&](int kt) {
        uint32_t st = smb + 8192 + (kt & 1) * ATT_STAGE;
        const bf16* pp[3] = {Kh, Vh, Vl};
        #pragma unroll
        for (int it = 0; it < 12; it++) {
            int pl = it >> 2;
            int row = (it & 3) * 16 + (tid >> 3);
            int g = tid & 7;
            cp_async16(st + pl * 8192 + sw128(row, g),
                       pp[pl] + (size_t)(b * SEQ + kt * 64 + row) * CH + h * DH + g * 8);
        }
    };
    issue_tile(0);
    CP_COMMIT();

    const float* bp0 = bias +
        ((size_t)(b * NH + h) * SEQ + q0 + w * 16 + (lane >> 2)) * SEQ + (lane & 3) * 2;

    // preload bias for tile 0 into registers
    float2 bufA[8], bufB[8];
    #pragma unroll
    for (int n = 0; n < 8; n++) {
        bufA[n] = *(const float2*)(bp0 + n * 8);
        bufB[n] = *(const float2*)(bp0 + (size_t)8 * SEQ + n * 8);
    }

    CP_WAIT(0);
    __syncthreads();

    uint32_t qhf[4][4];
    {
        int qrow = w * 16 + (lane & 15);
        #pragma unroll
        for (int ks = 0; ks < 4; ks++) {
            uint32_t so = sw128(qrow, ks * 2 + (lane >> 4));
            LDSM4(qhf[ks][0], qhf[ks][1], qhf[ks][2], qhf[ks][3], smb + so);
        }
    }

    float o[8][4];
    #pragma unroll
    for (int n = 0; n < 8; n++)
        #pragma unroll
        for (int j = 0; j < 4; j++) o[n][j] = 0.f;
    float miA = -1e30f, miB = -1e30f, liA = 0.f, liB = 0.f;

    for (int kt = 0; kt < 16; kt++) {
        if (kt + 1 < 16) { issue_tile(kt + 1); CP_COMMIT(); }

        uint32_t sKh = smb + 8192 + (kt & 1) * ATT_STAGE;
        uint32_t sVh = sKh + 8192;
        uint32_t sVl = sKh + 16384;

        float s[8][4];
        #pragma unroll
        for (int n = 0; n < 8; n++)
            #pragma unroll
            for (int j = 0; j < 4; j++) s[n][j] = 0.f;

        int krow_base = ((lane >> 4) & 1) * 8 + (lane & 7);
        int kg_base = (lane >> 3) & 1;
        #pragma unroll
        for (int ks = 0; ks < 4; ks++) {
            int kg = ks * 2 + kg_base;
            #pragma unroll
            for (int np = 0; np < 4; np++) {
                uint32_t so = sw128(np * 16 + krow_base, kg);
                uint32_t h0, h1, h2, h3;
                LDSM4(h0, h1, h2, h3, sKh + so);
                MMA_BF16_2(s[np * 2], qhf[ks], h0, h1);
                MMA_BF16_2(s[np * 2 + 1], qhf[ks], h2, h3);
            }
        }

        // consume preloaded bias for this tile
        #pragma unroll
        for (int n = 0; n < 8; n++) {
            s[n][0] = fmaf(s[n][0], ASCALE, bufA[n].x);
            s[n][1] = fmaf(s[n][1], ASCALE, bufA[n].y);
            s[n][2] = fmaf(s[n][2], ASCALE, bufB[n].x);
            s[n][3] = fmaf(s[n][3], ASCALE, bufB[n].y);
        }
        // issue bias loads for next tile (latency hidden below)
        if (kt + 1 < 16) {
            const float* bp = bp0 + (kt + 1) * 64;
            #pragma unroll
            for (int n = 0; n < 8; n++) {
                bufA[n] = *(const float2*)(bp + n * 8);
                bufB[n] = *(const float2*)(bp + (size_t)8 * SEQ + n * 8);
            }
        }

        float mA = -1e30f, mB = -1e30f;
        #pragma unroll
        for (int n = 0; n < 8; n++) {
            mA = fmaxf(mA, fmaxf(s[n][0], s[n][1]));
            mB = fmaxf(mB, fmaxf(s[n][2], s[n][3]));
        }
        mA = fmaxf(mA, __shfl_xor_sync(0xffffffffu, mA, 1));
        mA = fmaxf(mA, __shfl_xor_sync(0xffffffffu, mA, 2));
        mB = fmaxf(mB, __shfl_xor_sync(0xffffffffu, mB, 1));
        mB = fmaxf(mB, __shfl_xor_sync(0xffffffffu, mB, 2));
        float mnA = fmaxf(miA, mA), mnB = fmaxf(miB, mB);
        float corrA = __expf(miA - mnA), corrB = __expf(miB - mnB);
        miA = mnA; miB = mnB;
        float rsA = 0.f, rsB = 0.f;
        #pragma unroll
        for (int n = 0; n < 8; n++) {
            s[n][0] = __expf(s[n][0] - mnA);
            s[n][1] = __expf(s[n][1] - mnA);
            s[n][2] = __expf(s[n][2] - mnB);
            s[n][3] = __expf(s[n][3] - mnB);
            rsA += s[n][0] + s[n][1];
            rsB += s[n][2] + s[n][3];
        }
        rsA += __shfl_xor_sync(0xffffffffu, rsA, 1);
        rsA += __shfl_xor_sync(0xffffffffu, rsA, 2);
        rsB += __shfl_xor_sync(0xffffffffu, rsB, 1);
        rsB += __shfl_xor_sync(0xffffffffu, rsB, 2);
        liA = liA * corrA + rsA;
        liB = liB * corrB + rsB;
        #pragma unroll
        for (int n = 0; n < 8; n++) {
            o[n][0] *= corrA; o[n][1] *= corrA;
            o[n][2] *= corrB; o[n][3] *= corrB;
        }

        int vrow_base = ((lane >> 3) & 1) * 8 + (lane & 7);
        int vg_base = (lane >> 4) & 1;
        #pragma unroll
        for (int kk = 0; kk < 4; kk++) {
            uint32_t pah[4];
            #pragma unroll
            for (int q = 0; q < 2; q++) {
                int nf = kk * 2 + q;
                pah[q * 2 + 0] = pack_bf2(s[nf][0], s[nf][1]);
                pah[q * 2 + 1] = pack_bf2(s[nf][2], s[nf][3]);
            }
            #pragma unroll
            for (int dp = 0; dp < 4; dp++) {
                uint32_t so = sw128(kk * 16 + vrow_base, dp * 2 + vg_base);
                uint32_t r0, r1, r2, r3;
                LDSM4T(r0, r1, r2, r3, sVh + so);
                MMA_BF16_2(o[dp * 2], pah, r0, r1);
                MMA_BF16_2(o[dp * 2 + 1], pah, r2, r3);
                LDSM4T(r0, r1, r2, r3, sVl + so);
                MMA_BF16_2(o[dp * 2], pah, r0, r1);
                MMA_BF16_2(o[dp * 2 + 1], pah, r2, r3);
            }
        }

        if (kt + 1 < 16) { CP_WAIT(0); __syncthreads(); }
    }

    float invA = 1.0f / liA, invB = 1.0f / liB;
    size_t rowA = (size_t)(b * SEQ + q0 + w * 16 + (lane >> 2));
    #pragma unroll
    for (int n = 0; n < 8; n++) {
        int col = h * DH + n * 8 + (lane & 3) * 2;
        float f0 = o[n][0] * invA, f1 = o[n][1] * invA;
        float f2 = o[n][2] * invB, f3 = o[n][3] * invB;
        bf16 h0, h1, h2, h3, l0, l1, l2, l3;
        split_f(f0, h0, l0); split_f(f1, h1, l1);
        split_f(f2, h2, l2); split_f(f3, h3, l3);
        *(bf162*)(Oh + rowA * CH + col) = bf162(h0, h1);
        *(bf162*)(Ol + rowA * CH + col) = bf162(l0, l1);
        *(bf162*)(Oh + (rowA + 8) * CH + col) = bf162(h2, h3);
        *(bf162*)(Ol + (rowA + 8) * CH + col) = bf162(l2, l3);
    }
}

// ---------------- launch ------------------------------------------------------
extern "C" void kernel_launch(void* const* d_in, const int* in_sizes, int n_in,
                              void* d_out, int out_size) {
    const float* x         = (const float*)d_in[0];
    const float* context   = (const float*)d_in[1];
    const float* cond_BD   = (const float*)d_in[2];
    const float* attn_bias = (const float*)d_in[3];
    const float* ada_gss   = (const float*)d_in[4];
    const float* Wq        = (const float*)d_in[5];
    const float* Wk        = (const float*)d_in[6];
    const float* Wv        = (const float*)d_in[7];
    const float* Wo        = (const float*)d_in[8];
    const float* bo        = (const float*)d_in[9];
    const float* W1        = (const float*)d_in[10];
    const float* b1        = (const float*)d_in[11];
    const float* W2        = (const float*)d_in[12];
    const float* b2        = (const float*)d_in[13];
    float* out = (float*)d_out;

    float* x1_p;
    cudaGetSymbolAddress((void**)&x1_p, x1_buf);

    bf16 *wqh, *wql, *wkh, *wkl, *wvh, *wvl, *woh, *wol;
    bf16 *w1h, *w1l, *w2h, *w2l, *ch_, *cl_, *mh, *ml, *aoh, *aol, *hh, *hl;
    bf16 *qh, *kh, *vh, *vl;
    cudaGetSymbolAddress((void**)&wqh, wq_h); cudaGetSymbolAddress((void**)&wql, wq_l);
    cudaGetSymbolAddress((void**)&wkh, wk_h); cudaGetSymbolAddress((void**)&wkl, wk_l);
    cudaGetSymbolAddress((void**)&wvh, wv_h); cudaGetSymbolAddress((void**)&wvl, wv_l);
    cudaGetSymbolAddress((void**)&woh, wo_h); cudaGetSymbolAddress((void**)&wol, wo_l);
    cudaGetSymbolAddress((void**)&w1h, w1_h); cudaGetSymbolAddress((void**)&w1l, w1_l);
    cudaGetSymbolAddress((void**)&w2h, w2_h); cudaGetSymbolAddress((void**)&w2l, w2_l);
    cudaGetSymbolAddress((void**)&ch_, ctx_h); cudaGetSymbolAddress((void**)&cl_, ctx_l);
    cudaGetSymbolAddress((void**)&mh, mod_h);  cudaGetSymbolAddress((void**)&ml, mod_l);
    cudaGetSymbolAddress((void**)&aoh, ao_h);  cudaGetSymbolAddress((void**)&aol, ao_l);
    cudaGetSymbolAddress((void**)&hh, hb_h);   cudaGetSymbolAddress((void**)&hl, hb_l);
    cudaGetSymbolAddress((void**)&qh, q_h);
    cudaGetSymbolAddress((void**)&kh, k_h);
    cudaGetSymbolAddress((void**)&vh, v_h);    cudaGetSymbolAddress((void**)&vl, v_l);

    cudaFuncSetAttribute(attn_mma,
                         cudaFuncAttributeMaxDynamicSharedMemorySize, ATT_SMEM);
    cudaFuncSetAttribute(gemm_qkv,
                         cudaFuncAttributeMaxDynamicSharedMemorySize, GEMM_SMEM);
    cudaFuncSetAttribute(gemm_bf3<1>,
                         cudaFuncAttributeMaxDynamicSharedMemorySize, GEMM_SMEM);
    cudaFuncSetAttribute(gemm_bf3<2>,
                         cudaFuncAttributeMaxDynamicSharedMemorySize, GEMM_SMEM);
    cudaFuncSetAttribute(gemm_bf3<3>,
                         cudaFuncAttributeMaxDynamicSharedMemorySize, GEMM_SMEM);

    // 0: all seven splits + LN(x) in one launch
    PrepArgs pa;
    pa.src[0] = context; pa.hi[0] = ch_; pa.lo[0] = cl_; pa.n4[0] = NROWS * CH / 4;
    pa.src[1] = W1;      pa.hi[1] = w1h; pa.lo[1] = w1l; pa.n4[1] = FFNDIM * CH / 4;
    pa.src[2] = W2;      pa.hi[2] = w2h; pa.lo[2] = w2l; pa.n4[2] = FFNDIM * CH / 4;
    pa.src[3] = Wq;      pa.hi[3] = wqh; pa.lo[3] = wql; pa.n4[3] = CH * CH / 4;
    pa.src[4] = Wk;      pa.hi[4] = wkh; pa.lo[4] = wkl; pa.n4[4] = CH * CH / 4;
    pa.src[5] = Wv;      pa.hi[5] = wvh; pa.lo[5] = wvl; pa.n4[5] = CH * CH / 4;
    pa.src[6] = Wo;      pa.hi[6] = woh; pa.lo[6] = wol; pa.n4[6] = CH * CH / 4;
    pa.x = x; pa.ada = ada_gss; pa.cond = cond_BD; pa.mh = mh; pa.ml = ml;
    prep_kernel<<<dim3(1024, 11), 256>>>(pa);

    // 1: Q/K/V projections (Q, K: 2-term bf16-out; V: 3-term split-out)
    QkvArgs qa;
    qa.ah[0] = mh;  qa.al[0] = nullptr; qa.bh[0] = wqh; qa.bl[0] = wql;
    qa.yh[0] = qh;  qa.yl[0] = nullptr;
    qa.ah[1] = ch_; qa.al[1] = nullptr; qa.bh[1] = wkh; qa.bl[1] = wkl;
    qa.yh[1] = kh;  qa.yl[1] = nullptr;
    qa.ah[2] = ch_; qa.al[2] = cl_;     qa.bh[2] = wvh; qa.bl[2] = wvl;
    qa.yh[2] = vh;  qa.yl[2] = vl;
    gemm_qkv<<<dim3(8, 32, 3), 256, GEMM_SMEM>>>(qa);

    // 2: fused attention
    attn_mma<<<dim3(NB * NH, SEQ / 64), 128, ATT_SMEM>>>(qh, kh, vh, vl,
                                                         attn_bias, aoh, aol);

    // 3: x1 = x + (ao @ Wo^T + bo) * gamma1
    gemm_bf3<1><<<dim3(8, 32), 256, GEMM_SMEM>>>(aoh, aol, woh, wol, x1_p,
                                                 nullptr, nullptr,
                                                 NROWS, CH, CH,
                                                 bo, ada_gss, cond_BD, x);

    // 4: mod_f = LN(x1)*(1+scale2)+shift2
    ln_mod_kernel<<<NROWS, 256>>>(x1_p, ada_gss, cond_BD, mh, ml, 3, 5);

    // 5: h = gelu(mod_f @ W1^T + b1)
    gemm_bf3<2><<<dim3(32, 32), 256, GEMM_SMEM>>>(mh, ml, w1h, w1l, nullptr,
                                                  hh, hl,
                                                  NROWS, FFNDIM, CH,
                                                  b1, nullptr, nullptr, nullptr);

    // 6: out = x1 + (h @ W2^T + b2) * gamma2
    gemm_bf3<3><<<dim3(8, 32), 256, GEMM_SMEM>>>(hh, hl, w2h, w2l, out,
                                                 nullptr, nullptr,
                                                 NROWS, CH, FFNDIM,
                                                 b2, ada_gss + CH, cond_BD + CH,
                                                 x1_p);
}